// round 12
// baseline (speedup 1.0000x reference)
#include <cuda_runtime.h>

// Problem constants
#define Bsz 128
#define Cch 64
#define Hh  32
#define Tt  256
#define BG  8    // batches per block
#define IP  4    // hidden rows per thread
// k-split: each thread covers 16 of the 32 k-terms for its 4 rows.
// threads = 2 dirs * BG * 8 g * 2 kh = 256 (8 warps); 2 CTAs resident/SM.
// Warp = 32 consecutive tids = g(8) x kh(2) x b(2): ALL h-exchange intra-warp.

typedef unsigned long long u64;

__device__ __forceinline__ u64 ffma2(u64 a, u64 b, u64 c) {
    u64 d;
    asm("fma.rn.f32x2 %0, %1, %2, %3;" : "=l"(d) : "l"(a), "l"(b), "l"(c));
    return d;
}
__device__ __forceinline__ u64 pack2(float lo, float hi) {
    u64 r;
    asm("mov.b64 %0, {%1, %2};" : "=l"(r) : "f"(lo), "f"(hi));
    return r;
}
__device__ __forceinline__ void unpack2(u64 v, float& lo, float& hi) {
    asm("mov.b64 {%0, %1}, %2;" : "=f"(lo), "=f"(hi) : "l"(v));
}

__global__ __launch_bounds__(256, 2)
void mrnn_kernel(const float* __restrict__ x,  const float* __restrict__ m,
                 const float* __restrict__ dd,
                 const float* __restrict__ Wf, const float* __restrict__ Vf,
                 const float* __restrict__ cf,
                 const float* __restrict__ Wb, const float* __restrict__ Vb,
                 const float* __restrict__ cb,
                 const float* __restrict__ U,  const float* __restrict__ c0,
                 float* __restrict__ out)
{
    // h state, double buffered: [buf][dir][b][40]  (stride 40 floats; every
    // quarter-warp LDS phase is an 8-lane broadcast of one address)
    __shared__ __align__(16) float hbuf[2 * 2 * BG * 40];   // 5120 B
    // per-direction projection contributions: [dir][b][t]
    __shared__ float sfb[2 * BG * Tt];                       // 16384 B

    const int tid = threadIdx.x;
    const int g   = tid & 7;          // row-group (8 per (dir,b))
    const int kh  = (tid >> 3) & 1;   // k-half: 0 -> k 0..15, 1 -> k 16..31
    const int b   = (tid >> 4) & 7;   // local batch
    const int dir = tid >> 7;         // 0 = forward, 1 = backward
    const int c   = blockIdx.y;
    const int b0  = blockIdx.x * BG;
    const int i0  = g * IP;

    // ---- preload per-thread weights into registers (half the k-range) ----
    const float* Wg = (dir ? Wb : Wf) + c * Hh * Hh;
    const float* Vg = (dir ? Vb : Vf) + c * Hh * 3;
    const float* cg = (dir ? cb : cf) + c * Hh;

    u64   w[IP][8];                  // W rows (16 k-terms), (even,odd) pairs
    float v0[IP], v1[IP], v2[IP], cbi[IP], uu[IP];
    #pragma unroll
    for (int i = 0; i < IP; i++) {
        const u64* wr = (const u64*)(Wg + (i0 + i) * Hh + kh * 16);
        #pragma unroll
        for (int j = 0; j < 8; j++) w[i][j] = __ldg(wr + j);
        v0[i]  = __ldg(Vg + (i0 + i) * 3 + 0);
        v1[i]  = __ldg(Vg + (i0 + i) * 3 + 1);
        v2[i]  = __ldg(Vg + (i0 + i) * 3 + 2);
        cbi[i] = __ldg(cg + i0 + i);
        uu[i]  = __ldg(U + c * 2 * Hh + dir * Hh + i0 + i);
    }

    const long bc = (long)(b0 + b) * Cch * Tt + (long)c * Tt;
    const float* xp = x  + bc;
    const float* mp = m  + bc;
    const float* dp = dd + bc;

    const int hrow0 = (dir * BG + b) * 40;             // buffer 0
    const int hrow1 = (2 * BG + dir * BG + b) * 40;    // buffer 1
    float* srow = &sfb[(dir * BG + b) * Tt];

    // zero own h rows (h0 = 0); intra-warp visibility only
    if (kh == 0) {
        *(float4*)(&hbuf[hrow0 + i0]) = make_float4(0.f, 0.f, 0.f, 0.f);
        *(float4*)(&hbuf[hrow1 + i0]) = make_float4(0.f, 0.f, 0.f, 0.f);
    }
    __syncwarp();

    // input for step n reads padded index: q = max(n-1,0), tt = dir ? T-1-q : q
    const int tt0 = dir ? (Tt - 1) : 0;
    float vx = __ldg(xp + tt0);
    float vm = __ldg(mp + tt0);
    float vd = __ldg(dp + tt0);

    float sprev = 0.f;   // deferred projection value from previous step
    int   tprev = 0;

    // ---- T sequential RNN steps (warp-independent: no block barrier) ----
    #pragma unroll 2
    for (int n = 0; n < Tt; n++) {
        // prefetch inputs for step n+1 (q_next = n; clamps naturally at n=T-1)
        // NOTE: ttn also equals this step's output time index tout.
        const int ttn = dir ? (Tt - 1 - n) : n;
        const float nvx = __ldg(xp + ttn);
        const float nvm = __ldg(mp + ttn);
        const float nvd = __ldg(dp + ttn);

        const int rb = (n & 1) ? hrow1 : hrow0;
        const int wb = (n & 1) ? hrow0 : hrow1;
        // this thread reads only its 16-element k-half of h
        const ulonglong2* hr = (const ulonglong2*)&hbuf[rb + kh * 16];
        float*            hw = &hbuf[wb];

        // kh=0 seeds bias + V*v in lane-lo; kh=1 seeds zero (added once)
        u64 acc[IP];
        #pragma unroll
        for (int i = 0; i < IP; i++) {
            const float seed = kh ? 0.f
                : fmaf(v2[i], vd, fmaf(v1[i], vm, fmaf(v0[i], vx, cbi[i])));
            acc[i] = pack2(seed, 0.f);
        }

        // half matvec: 4 broadcast LDS.128 + 32 packed FMA2 (64 MACs)
        #pragma unroll
        for (int j = 0; j < 4; j++) {
            const ulonglong2 hp = hr[j];
            #pragma unroll
            for (int i = 0; i < IP; i++) {
                acc[i] = ffma2(w[i][2 * j],     hp.x, acc[i]);
                acc[i] = ffma2(w[i][2 * j + 1], hp.y, acc[i]);
            }
        }

        // combine: local lo+hi, then add partner k-half (lane xor 8)
        float p[IP];
        #pragma unroll
        for (int i = 0; i < IP; i++) {
            float lo, hi; unpack2(acc[i], lo, hi);
            p[i] = lo + hi;
        }
        float hn[IP];
        float s = 0.f;
        #pragma unroll
        for (int i = 0; i < IP; i++) {
            const float q = __shfl_xor_sync(0xffffffffu, p[i], 8);
            hn[i] = fmaxf(p[i] + q, 0.f);
            s = fmaf(uu[i], hn[i], s);          // fused U projection
        }

        if (kh == 0)   // both halves hold identical hn; store once
            *(float4*)(hw + i0) = make_float4(hn[0], hn[1], hn[2], hn[3]);

        __syncwarp();   // order hbuf STS before next step's LDS (intra-warp)

        // DEFERRED reduce of previous step's projection: overlaps the next
        // step's LDS/FMA stream instead of sitting on the recurrence path.
        if (n) {
            float r = sprev;
            r += __shfl_xor_sync(0xffffffffu, r, 1, 8);
            r += __shfl_xor_sync(0xffffffffu, r, 2, 8);
            r += __shfl_xor_sync(0xffffffffu, r, 4, 8);
            if ((tid & 15) == 0) srow[tprev] = r;
        }
        sprev = s; tprev = ttn;

        vx = nvx; vm = nvm; vd = nvd;
    }

    // tail: reduce + store the final step's projection
    {
        float r = sprev;
        r += __shfl_xor_sync(0xffffffffu, r, 1, 8);
        r += __shfl_xor_sync(0xffffffffu, r, 2, 8);
        r += __shfl_xor_sync(0xffffffffu, r, 4, 8);
        if ((tid & 15) == 0) srow[tprev] = r;
    }

    __syncthreads();    // single block barrier: fwd+bwd sfb both complete

    // ---- combine fwd + bwd contributions, final relu, coalesced store ----
    const float c0c = __ldg(c0 + c);
    for (int idx = tid; idx < BG * Tt; idx += 256) {
        const int bb = idx >> 8;     // local batch
        const int t  = idx & 255;
        const float v = fmaxf(sfb[bb * Tt + t] + sfb[(BG + bb) * Tt + t] + c0c, 0.f);
        out[(long)(b0 + bb) * Cch * Tt + (long)c * Tt + t] = v;
    }
}

extern "C" void kernel_launch(void* const* d_in, const int* in_sizes, int n_in,
                              void* d_out, int out_size)
{
    const float* x  = (const float*)d_in[0];
    const float* m  = (const float*)d_in[1];
    const float* d  = (const float*)d_in[2];
    const float* Wf = (const float*)d_in[3];
    const float* Vf = (const float*)d_in[4];
    const float* cf = (const float*)d_in[5];
    const float* Wb = (const float*)d_in[6];
    const float* Vb = (const float*)d_in[7];
    const float* cb = (const float*)d_in[8];
    const float* U  = (const float*)d_in[9];
    const float* c0 = (const float*)d_in[10];

    dim3 grid(Bsz / BG, Cch);   // 16 x 64 = 1024 blocks, 2 CTAs resident/SM
    mrnn_kernel<<<grid, 256>>>(x, m, d, Wf, Vf, cf, Wb, Vb, cb, U, c0,
                               (float*)d_out);
}

// round 13
// speedup vs baseline: 1.0682x; 1.0682x over previous
#include <cuda_runtime.h>

// Problem constants
#define Bsz 128
#define Cch 64
#define Hh  32
#define Tt  256
#define BG  16   // batches per block (two sets of 8: P0 = bq, P1 = bq+8)
#define IP  4    // hidden rows per thread
#define BOFF (Cch * Tt)   // element stride between consecutive batches
// threads = 2 dirs * 8 bq * 8 g = 128 (4 warps); 2 CTAs resident per SM.
// Each thread advances TWO independent recurrences (bq and bq+8) with the
// SAME W registers, phase-offset inside the loop body for self-covering ILP.

typedef unsigned long long u64;

__device__ __forceinline__ u64 ffma2(u64 a, u64 b, u64 c) {
    u64 d;
    asm("fma.rn.f32x2 %0, %1, %2, %3;" : "=l"(d) : "l"(a), "l"(b), "l"(c));
    return d;
}
__device__ __forceinline__ u64 pack2(float lo, float hi) {
    u64 r;
    asm("mov.b64 %0, {%1, %2};" : "=l"(r) : "f"(lo), "f"(hi));
    return r;
}
__device__ __forceinline__ void unpack2(u64 v, float& lo, float& hi) {
    asm("mov.b64 {%0, %1}, %2;" : "=f"(lo), "=f"(hi) : "l"(v));
}

__global__ __launch_bounds__(128, 2)
void mrnn_kernel(const float* __restrict__ x,  const float* __restrict__ m,
                 const float* __restrict__ dd,
                 const float* __restrict__ Wf, const float* __restrict__ Vf,
                 const float* __restrict__ cf,
                 const float* __restrict__ Wb, const float* __restrict__ Vb,
                 const float* __restrict__ cb,
                 const float* __restrict__ U,  const float* __restrict__ c0,
                 float* __restrict__ out)
{
    // h state, double buffered: [buf][dir][bb][40]  (stride 40 floats; the 4
    // bq-rows inside a warp land on disjoint bank spans -> broadcast LDS.128)
    __shared__ __align__(16) float hbuf[2 * 2 * BG * 40];   // 10240 B
    // per-direction projection contributions: [dir][bb][t]
    __shared__ float sfb[2 * BG * Tt];                       // 32768 B

    const int tid = threadIdx.x;
    const int g   = tid & 7;          // i-group (8 per (dir,bb)) - intra-warp
    const int bq  = (tid >> 3) & 7;   // base batch (P0); P1 = bq + 8
    const int dir = tid >> 6;         // 0 = forward (warps 0-1), 1 = backward
    const int c   = blockIdx.y;
    const int b0  = blockIdx.x * BG;
    const int i0  = g * IP;

    // ---- preload per-thread weights into registers (shared by both streams) ----
    const float* Wg = (dir ? Wb : Wf) + c * Hh * Hh;
    const float* Vg = (dir ? Vb : Vf) + c * Hh * 3;
    const float* cg = (dir ? cb : cf) + c * Hh;

    u64   w[IP][16];                 // W rows, packed as (k even, k odd) pairs
    float v0[IP], v1[IP], v2[IP], cbi[IP], uu[IP];
    #pragma unroll
    for (int i = 0; i < IP; i++) {
        const u64* wr = (const u64*)(Wg + (i0 + i) * Hh);
        #pragma unroll
        for (int j = 0; j < 16; j++) w[i][j] = __ldg(wr + j);
        v0[i]  = __ldg(Vg + (i0 + i) * 3 + 0);
        v1[i]  = __ldg(Vg + (i0 + i) * 3 + 1);
        v2[i]  = __ldg(Vg + (i0 + i) * 3 + 2);
        cbi[i] = __ldg(cg + i0 + i);
        uu[i]  = __ldg(U + c * 2 * Hh + dir * Hh + i0 + i);
    }

    const long bc = (long)(b0 + bq) * Cch * Tt + (long)c * Tt;
    const float* xp = x  + bc;       // P1 stream at +8*BOFF
    const float* mp = m  + bc;
    const float* dp = dd + bc;

    const int hrow0 = (dir * BG + bq) * 40;             // P0, buffer 0
    const int hrow1 = (2 * BG + dir * BG + bq) * 40;    // P0, buffer 1
    // P1 rows are +8*40 = +320 floats
    float* srow0 = &sfb[(dir * BG + bq) * Tt];
    float* srow1 = srow0 + 8 * Tt;

    // zero own h rows (h0 = 0) for both streams/buffers
    *(float4*)(&hbuf[hrow0 + i0])       = make_float4(0.f, 0.f, 0.f, 0.f);
    *(float4*)(&hbuf[hrow0 + 320 + i0]) = make_float4(0.f, 0.f, 0.f, 0.f);
    *(float4*)(&hbuf[hrow1 + i0])       = make_float4(0.f, 0.f, 0.f, 0.f);
    *(float4*)(&hbuf[hrow1 + 320 + i0]) = make_float4(0.f, 0.f, 0.f, 0.f);
    __syncwarp();

    // input for step n reads padded index: q = max(n-1,0), tt = dir ? T-1-q : q
    const int tt0 = dir ? (Tt - 1) : 0;
    float vx0 = __ldg(xp + tt0),            vm0 = __ldg(mp + tt0),            vd0 = __ldg(dp + tt0);
    float vx1 = __ldg(xp + 8 * BOFF + tt0), vm1 = __ldg(mp + 8 * BOFF + tt0), vd1 = __ldg(dp + 8 * BOFF + tt0);

    float sprev1 = 0.f;   // P1 projection deferred one full step
    int   tprev1 = 0;

    // ---- T sequential RNN steps, two interleaved streams per warp ----
    #pragma unroll 2
    for (int n = 0; n < Tt; n++) {
        // ttn = input index for step n+1; ALSO this step's output time index.
        const int ttn = dir ? (Tt - 1 - n) : n;

        const int rb = (n & 1) ? hrow1 : hrow0;
        const int wb = (n & 1) ? hrow0 : hrow1;

        // ================= stream P0 =================
        const ulonglong2* hr0 = (const ulonglong2*)&hbuf[rb];
        float*            hw0 = &hbuf[wb];

        u64 acc[IP];
        #pragma unroll
        for (int i = 0; i < IP; i++)
            acc[i] = pack2(fmaf(v0[i], vx0, cbi[i]),
                           fmaf(v2[i], vd0, v1[i] * vm0));

        // deferred reduce of P1's PREVIOUS projection: sits in P0's LDS shadow
        if (n) {
            float r = sprev1;
            r += __shfl_xor_sync(0xffffffffu, r, 1, 8);
            r += __shfl_xor_sync(0xffffffffu, r, 2, 8);
            r += __shfl_xor_sync(0xffffffffu, r, 4, 8);
            if (g == 0) srow1[tprev1] = r;
        }

        #pragma unroll
        for (int j = 0; j < 8; j++) {
            const ulonglong2 hp = hr0[j];
            #pragma unroll
            for (int i = 0; i < IP; i++) {
                acc[i] = ffma2(w[i][2 * j],     hp.x, acc[i]);
                acc[i] = ffma2(w[i][2 * j + 1], hp.y, acc[i]);
            }
        }

        float s0 = 0.f;
        {
            float hn[IP];
            #pragma unroll
            for (int i = 0; i < IP; i++) {
                float lo, hi; unpack2(acc[i], lo, hi);
                hn[i] = fmaxf(lo + hi, 0.f);
                s0 = fmaf(uu[i], hn[i], s0);
            }
            *(float4*)(hw0 + i0) = make_float4(hn[0], hn[1], hn[2], hn[3]);
        }

        // prefetch P0 inputs for step n+1 (overlaps P1 section)
        const float nvx0 = __ldg(xp + ttn);
        const float nvm0 = __ldg(mp + ttn);
        const float nvd0 = __ldg(dp + ttn);

        // ================= stream P1 =================
        const ulonglong2* hr1 = (const ulonglong2*)&hbuf[rb + 320];
        float*            hw1 = &hbuf[wb + 320];

        u64 acd[IP];
        #pragma unroll
        for (int i = 0; i < IP; i++)
            acd[i] = pack2(fmaf(v0[i], vx1, cbi[i]),
                           fmaf(v2[i], vd1, v1[i] * vm1));

        // reduce P0's projection inside P1's burst window
        {
            float r = s0;
            r += __shfl_xor_sync(0xffffffffu, r, 1, 8);
            r += __shfl_xor_sync(0xffffffffu, r, 2, 8);
            r += __shfl_xor_sync(0xffffffffu, r, 4, 8);
            if (g == 0) srow0[ttn] = r;
        }

        #pragma unroll
        for (int j = 0; j < 8; j++) {
            const ulonglong2 hp = hr1[j];
            #pragma unroll
            for (int i = 0; i < IP; i++) {
                acd[i] = ffma2(w[i][2 * j],     hp.x, acd[i]);
                acd[i] = ffma2(w[i][2 * j + 1], hp.y, acd[i]);
            }
        }

        float s1 = 0.f;
        {
            float hn[IP];
            #pragma unroll
            for (int i = 0; i < IP; i++) {
                float lo, hi; unpack2(acd[i], lo, hi);
                hn[i] = fmaxf(lo + hi, 0.f);
                s1 = fmaf(uu[i], hn[i], s1);
            }
            *(float4*)(hw1 + i0) = make_float4(hn[0], hn[1], hn[2], hn[3]);
        }
        sprev1 = s1; tprev1 = ttn;

        // prefetch P1 inputs for step n+1
        const float nvx1 = __ldg(xp + 8 * BOFF + ttn);
        const float nvm1 = __ldg(mp + 8 * BOFF + ttn);
        const float nvd1 = __ldg(dp + 8 * BOFF + ttn);

        vx0 = nvx0; vm0 = nvm0; vd0 = nvd0;
        vx1 = nvx1; vm1 = nvm1; vd1 = nvd1;

        __syncwarp();   // ONE barrier orders both streams' STS vs next LDS
    }

    // tail: reduce + store P1's final projection
    {
        float r = sprev1;
        r += __shfl_xor_sync(0xffffffffu, r, 1, 8);
        r += __shfl_xor_sync(0xffffffffu, r, 2, 8);
        r += __shfl_xor_sync(0xffffffffu, r, 4, 8);
        if (g == 0) srow1[tprev1] = r;
    }

    __syncthreads();    // single block barrier: fwd+bwd sfb both complete

    // ---- combine fwd + bwd contributions, final relu, coalesced store ----
    const float c0c = __ldg(c0 + c);
    for (int idx = tid; idx < BG * Tt; idx += 128) {
        const int bb = idx >> 8;     // local batch
        const int t  = idx & 255;
        const float v = fmaxf(sfb[bb * Tt + t] + sfb[(BG + bb) * Tt + t] + c0c, 0.f);
        out[(long)(b0 + bb) * Cch * Tt + (long)c * Tt + t] = v;
    }
}

extern "C" void kernel_launch(void* const* d_in, const int* in_sizes, int n_in,
                              void* d_out, int out_size)
{
    const float* x  = (const float*)d_in[0];
    const float* m  = (const float*)d_in[1];
    const float* d  = (const float*)d_in[2];
    const float* Wf = (const float*)d_in[3];
    const float* Vf = (const float*)d_in[4];
    const float* cf = (const float*)d_in[5];
    const float* Wb = (const float*)d_in[6];
    const float* Vb = (const float*)d_in[7];
    const float* cb = (const float*)d_in[8];
    const float* U  = (const float*)d_in[9];
    const float* c0 = (const float*)d_in[10];

    dim3 grid(Bsz / BG, Cch);   // 8 x 64 = 512 blocks, 2 CTAs resident per SM
    mrnn_kernel<<<grid, 128>>>(x, m, d, Wf, Vf, cf, Wb, Vb, cb, U, c0,
                               (float*)d_out);
}

// round 14
// speedup vs baseline: 1.1643x; 1.0899x over previous
#include <cuda_runtime.h>

// Problem constants
#define Bsz 128
#define Cch 64
#define Hh  32
#define Tt  256
#define BG  8    // batches per block
#define IP  4    // hidden rows per thread
// threads = 2 dirs * BG * (Hh/IP) = 2*8*8 = 128 (4 warps); 2 CTAs resident/SM

typedef unsigned long long u64;

__device__ __forceinline__ u64 ffma2(u64 a, u64 b, u64 c) {
    u64 d;
    asm("fma.rn.f32x2 %0, %1, %2, %3;" : "=l"(d) : "l"(a), "l"(b), "l"(c));
    return d;
}
__device__ __forceinline__ void unpack2(u64 v, float& lo, float& hi) {
    asm("mov.b64 {%0, %1}, %2;" : "=f"(lo), "=f"(hi) : "l"(v));
}

__global__ __launch_bounds__(128, 2)
void mrnn_kernel(const float* __restrict__ x,  const float* __restrict__ m,
                 const float* __restrict__ dd,
                 const float* __restrict__ Wf, const float* __restrict__ Vf,
                 const float* __restrict__ cf,
                 const float* __restrict__ Wb, const float* __restrict__ Vb,
                 const float* __restrict__ cb,
                 const float* __restrict__ U,  const float* __restrict__ c0,
                 float* __restrict__ out)
{
    // h state, double buffered: [buf][dir][b][40]  (stride 40 floats => the 4
    // batch-rows inside a warp land on disjoint bank spans, broadcast LDS.128)
    __shared__ __align__(16) float hbuf[2 * 2 * BG * 40];   // 5120 B
    // per-direction projection contributions: [dir][b][t]
    __shared__ float sfb[2 * BG * Tt];                       // 16384 B

    const int tid = threadIdx.x;
    const int g   = tid & 7;          // i-group (8 per (dir,b)) - intra-warp
    const int b   = (tid >> 3) & 7;   // local batch
    const int dir = tid >> 6;         // 0 = forward (warps 0-1), 1 = backward
    const int c   = blockIdx.y;
    const int b0  = blockIdx.x * BG;
    const int i0  = g * IP;

    // ---- preload per-thread weights into registers ----
    const float* Wg = (dir ? Wb : Wf) + c * Hh * Hh;
    const float* Vg = (dir ? Vb : Vf) + c * Hh * 3;
    const float* cg = (dir ? cb : cf) + c * Hh;

    u64   w[IP][16];                 // W rows, packed as (k even, k odd) pairs
    float v0[IP], v1[IP], v2[IP], cbi[IP], uu[IP];
    #pragma unroll
    for (int i = 0; i < IP; i++) {
        const u64* wr = (const u64*)(Wg + (i0 + i) * Hh);
        #pragma unroll
        for (int j = 0; j < 16; j++) w[i][j] = __ldg(wr + j);
        v0[i]  = __ldg(Vg + (i0 + i) * 3 + 0);
        v1[i]  = __ldg(Vg + (i0 + i) * 3 + 1);
        v2[i]  = __ldg(Vg + (i0 + i) * 3 + 2);
        cbi[i] = __ldg(cg + i0 + i);
        uu[i]  = __ldg(U + c * 2 * Hh + dir * Hh + i0 + i);
    }

    const long bc = (long)(b0 + b) * Cch * Tt + (long)c * Tt;
    const float* xp = x  + bc;
    const float* mp = m  + bc;
    const float* dp = dd + bc;

    const int hrow0 = (dir * BG + b) * 40;             // buffer 0
    const int hrow1 = (2 * BG + dir * BG + b) * 40;    // buffer 1
    float* srow = &sfb[(dir * BG + b) * Tt];

    // zero own h rows (h0 = 0); intra-warp visibility only
    *(float4*)(&hbuf[hrow0 + i0]) = make_float4(0.f, 0.f, 0.f, 0.f);
    *(float4*)(&hbuf[hrow1 + i0]) = make_float4(0.f, 0.f, 0.f, 0.f);
    __syncwarp();

    const u64 zero2 = 0ull;          // packed (0.f, 0.f)

    float sprev = 0.f;   // deferred projection value from previous step
    int   tprev = 0;

    // ---- T sequential RNN steps (warp-independent: no block barrier) ----
    #pragma unroll 2
    for (int n = 0; n < Tt; n++) {
        // input index for step n: q = max(n-1, 0); tt = dir ? T-1-q : q
        // output time index for step n: ttn = dir ? T-1-n : n
        const int ttn = dir ? (Tt - 1 - n) : n;
        const int tti = dir ? (n ? ttn + 1 : Tt - 1) : (n ? n - 1 : 0);

        const int rb = (n & 1) ? hrow1 : hrow0;
        const int wb = (n & 1) ? hrow0 : hrow1;
        const ulonglong2* hr = (const ulonglong2*)&hbuf[rb];
        float*            hw = &hbuf[wb];

        // issue ALL h loads first (fills the LSU early)
        u64 hp[16];
        #pragma unroll
        for (int j = 0; j < 8; j++) {
            const ulonglong2 q = hr[j];
            hp[2 * j] = q.x; hp[2 * j + 1] = q.y;
        }

        // DEFERRED reduce of previous step's projection: executes in the
        // LDS-latency shadow (pure shfl/alu, no memory dependency on hbuf).
        if (n) {
            float r = sprev;
            r += __shfl_xor_sync(0xffffffffu, r, 1, 8);
            r += __shfl_xor_sync(0xffffffffu, r, 2, 8);
            r += __shfl_xor_sync(0xffffffffu, r, 4, 8);
            if (g == 0) srow[tprev] = r;
        }

        // inputs for this step: L1-hit loads, consumed only in the epilogue
        const float vx = __ldg(xp + tti);
        const float vm = __ldg(mp + tti);
        const float vd = __ldg(dp + tti);

        // 32x32 matvec: chains start DIRECTLY from h data (seed folded later)
        u64 acc[IP];
        #pragma unroll
        for (int i = 0; i < IP; i++)
            acc[i] = ffma2(w[i][0], hp[0], zero2);
        #pragma unroll
        for (int j = 1; j < 16; j++) {
            #pragma unroll
            for (int i = 0; i < IP; i++)
                acc[i] = ffma2(w[i][j], hp[j], acc[i]);
        }

        // epilogue: fold seed (bias + V*v), relu, fused U projection
        float hn[IP];
        float s = 0.f;
        #pragma unroll
        for (int i = 0; i < IP; i++) {
            const float seed = fmaf(v2[i], vd,
                               fmaf(v1[i], vm,
                               fmaf(v0[i], vx, cbi[i])));
            float lo, hi; unpack2(acc[i], lo, hi);
            hn[i] = fmaxf((lo + hi) + seed, 0.f);
            s = fmaf(uu[i], hn[i], s);
        }

        *(float4*)(hw + i0) = make_float4(hn[0], hn[1], hn[2], hn[3]);

        sprev = s; tprev = ttn;

        __syncwarp();   // order hbuf STS before next step's LDS (intra-warp)
    }

    // tail: reduce + store the final step's projection
    {
        float r = sprev;
        r += __shfl_xor_sync(0xffffffffu, r, 1, 8);
        r += __shfl_xor_sync(0xffffffffu, r, 2, 8);
        r += __shfl_xor_sync(0xffffffffu, r, 4, 8);
        if (g == 0) srow[tprev] = r;
    }

    __syncthreads();    // single block barrier: fwd+bwd sfb both complete

    // ---- combine fwd + bwd contributions, final relu, coalesced store ----
    const float c0c = __ldg(c0 + c);
    for (int idx = tid; idx < BG * Tt; idx += 128) {
        const int bb = idx >> 8;     // local batch
        const int t  = idx & 255;
        const float v = fmaxf(sfb[bb * Tt + t] + sfb[(BG + bb) * Tt + t] + c0c, 0.f);
        out[(long)(b0 + bb) * Cch * Tt + (long)c * Tt + t] = v;
    }
}

extern "C" void kernel_launch(void* const* d_in, const int* in_sizes, int n_in,
                              void* d_out, int out_size)
{
    const float* x  = (const float*)d_in[0];
    const float* m  = (const float*)d_in[1];
    const float* d  = (const float*)d_in[2];
    const float* Wf = (const float*)d_in[3];
    const float* Vf = (const float*)d_in[4];
    const float* cf = (const float*)d_in[5];
    const float* Wb = (const float*)d_in[6];
    const float* Vb = (const float*)d_in[7];
    const float* cb = (const float*)d_in[8];
    const float* U  = (const float*)d_in[9];
    const float* c0 = (const float*)d_in[10];

    dim3 grid(Bsz / BG, Cch);   // 16 x 64 = 1024 blocks, 2 CTAs resident/SM
    mrnn_kernel<<<grid, 128>>>(x, m, d, Wf, Vf, cf, Wb, Vb, cb, U, c0,
                               (float*)d_out);
}